// round 1
// baseline (speedup 1.0000x reference)
#include <cuda_runtime.h>
#include <math.h>
#include <stdint.h>

// ----------------------------------------------------------------------------
// KAN block: out = kan_layer(kan_layer(x, W1), W2)
// kan_layer(x) = silu(x) @ w_base^T + bases(x) @ w_spline_flat^T
// where bases(x) : (N, in*8) order-3 B-spline values, w_spline (out, in, 8) is
// already K-major over flattened (i*8+g).
// ----------------------------------------------------------------------------

#define D_MODEL 512
#define D_FF    2048
#define GKN     8      // G + K spline bases per input
#define NTOK    4096   // B * S

// Scratch (device-global; no runtime allocation allowed)
__device__ float g_S1[(size_t)NTOK * D_MODEL];          //  8 MB  silu(x)
__device__ float g_B1[(size_t)NTOK * D_MODEL * GKN];    // 67 MB  bases(x)
__device__ float g_H [(size_t)NTOK * D_FF];             // 33 MB  hidden
__device__ float g_S2[(size_t)NTOK * D_FF];             // 33 MB  silu(h)
__device__ float g_B2[(size_t)NTOK * D_FF * GKN];       // 268 MB bases(h)

// ----------------------------------------------------------------------------
// Expansion: per element compute silu + 8 cubic B-spline bases (Cox-de Boor),
// matching the reference recursion exactly (half-open order-0 intervals).
// ----------------------------------------------------------------------------
__global__ void expand_kernel(const float* __restrict__ x,
                              const float* __restrict__ grid,
                              float* __restrict__ S,
                              float* __restrict__ Bs,
                              int total) {
    int idx = blockIdx.x * blockDim.x + threadIdx.x;
    if (idx >= total) return;

    float v = x[idx];
    S[idx] = v / (1.0f + expf(-v));

    float t[12];
#pragma unroll
    for (int j = 0; j < 12; j++) t[j] = grid[j];

    float b[11];
#pragma unroll
    for (int j = 0; j < 11; j++) b[j] = (v >= t[j] && v < t[j + 1]) ? 1.0f : 0.0f;

#pragma unroll
    for (int ord = 1; ord <= 3; ord++) {
#pragma unroll
        for (int i = 0; i < 11 - 1; i++) {
            if (i < 11 - ord) {
                float left  = (v - t[i]) / (t[i + ord] - t[i]);
                float right = (t[i + ord + 1] - v) / (t[i + ord + 1] - t[i + 1]);
                b[i] = left * b[i] + right * b[i + 1];
            }
        }
    }

    float4* dst = reinterpret_cast<float4*>(Bs) + (size_t)idx * 2;
    dst[0] = make_float4(b[0], b[1], b[2], b[3]);
    dst[1] = make_float4(b[4], b[5], b[6], b[7]);
}

// ----------------------------------------------------------------------------
// TN GEMM: C[m][n] (+)= sum_k A[m][k] * B[n][k]
// A: (M, Kt) row-major, B: (Nout, Kt) row-major (K-major), C: (M, Nout).
// 128x128 block tile, BK=16, 256 threads, 8x8 per-thread tile, double-buffered.
// M, Nout multiples of 128; Kt multiple of 16 (holds for all calls here).
// ----------------------------------------------------------------------------
#define BM 128
#define BN 128
#define BK 16

__global__ void __launch_bounds__(256, 2)
gemm_tn_kernel(const float* __restrict__ A, const float* __restrict__ B,
               float* __restrict__ C, int M, int Nout, int Kt, int accumulate) {
    __shared__ float As[2][BK][BM];
    __shared__ float Bs[2][BK][BN];

    const int tid = threadIdx.x;
    const int m0 = blockIdx.y * BM;
    const int n0 = blockIdx.x * BN;

    const float* Ab = A + (size_t)m0 * Kt;
    const float* Bb = B + (size_t)n0 * Kt;

    // loader mapping: thread loads rows r0 and r0+64, 4 floats at col c0
    const int r0 = tid >> 2;
    const int c0 = (tid & 3) * 4;

    float4 ra0, ra1, rb0, rb1;

    auto loadg = [&](int kt) {
        const float* ap = Ab + (size_t)kt * BK + c0;
        ra0 = *(const float4*)(ap + (size_t)r0 * Kt);
        ra1 = *(const float4*)(ap + (size_t)(r0 + 64) * Kt);
        const float* bp = Bb + (size_t)kt * BK + c0;
        rb0 = *(const float4*)(bp + (size_t)r0 * Kt);
        rb1 = *(const float4*)(bp + (size_t)(r0 + 64) * Kt);
    };
    auto store_smem = [&](int buf) {
        As[buf][c0 + 0][r0] = ra0.x;  As[buf][c0 + 1][r0] = ra0.y;
        As[buf][c0 + 2][r0] = ra0.z;  As[buf][c0 + 3][r0] = ra0.w;
        As[buf][c0 + 0][r0 + 64] = ra1.x;  As[buf][c0 + 1][r0 + 64] = ra1.y;
        As[buf][c0 + 2][r0 + 64] = ra1.z;  As[buf][c0 + 3][r0 + 64] = ra1.w;
        Bs[buf][c0 + 0][r0] = rb0.x;  Bs[buf][c0 + 1][r0] = rb0.y;
        Bs[buf][c0 + 2][r0] = rb0.z;  Bs[buf][c0 + 3][r0] = rb0.w;
        Bs[buf][c0 + 0][r0 + 64] = rb1.x;  Bs[buf][c0 + 1][r0 + 64] = rb1.y;
        Bs[buf][c0 + 2][r0 + 64] = rb1.z;  Bs[buf][c0 + 3][r0 + 64] = rb1.w;
    };

    float acc[8][8];
#pragma unroll
    for (int i = 0; i < 8; i++)
#pragma unroll
        for (int j = 0; j < 8; j++) acc[i][j] = 0.0f;

    const int tx = (tid & 15) * 8;   // n offset within tile
    const int ty = (tid >> 4) * 8;   // m offset within tile

    const int nk = Kt / BK;
    loadg(0);
    store_smem(0);
    __syncthreads();

    int buf = 0;
    for (int kt = 0; kt < nk; kt++) {
        const bool has_next = (kt + 1 < nk);
        if (has_next) loadg(kt + 1);

#pragma unroll
        for (int kk = 0; kk < BK; kk++) {
            float4 a0 = *(const float4*)&As[buf][kk][ty];
            float4 a1 = *(const float4*)&As[buf][kk][ty + 4];
            float4 b0 = *(const float4*)&Bs[buf][kk][tx];
            float4 b1 = *(const float4*)&Bs[buf][kk][tx + 4];
            float av[8] = {a0.x, a0.y, a0.z, a0.w, a1.x, a1.y, a1.z, a1.w};
            float bv[8] = {b0.x, b0.y, b0.z, b0.w, b1.x, b1.y, b1.z, b1.w};
#pragma unroll
            for (int i = 0; i < 8; i++)
#pragma unroll
                for (int j = 0; j < 8; j++)
                    acc[i][j] += av[i] * bv[j];
        }

        if (has_next) {
            store_smem(buf ^ 1);
            __syncthreads();
            buf ^= 1;
        }
    }

    // epilogue
    float* Cp = C + (size_t)(m0 + ty) * Nout + n0 + tx;
#pragma unroll
    for (int i = 0; i < 8; i++) {
        float* row = Cp + (size_t)i * Nout;
        float4 v0 = make_float4(acc[i][0], acc[i][1], acc[i][2], acc[i][3]);
        float4 v1 = make_float4(acc[i][4], acc[i][5], acc[i][6], acc[i][7]);
        if (accumulate) {
            float4 o0 = *(const float4*)(row);
            float4 o1 = *(const float4*)(row + 4);
            v0.x += o0.x; v0.y += o0.y; v0.z += o0.z; v0.w += o0.w;
            v1.x += o1.x; v1.y += o1.y; v1.z += o1.z; v1.w += o1.w;
        }
        *(float4*)(row)     = v0;
        *(float4*)(row + 4) = v1;
    }
}

// ----------------------------------------------------------------------------
// Launch
// ----------------------------------------------------------------------------
extern "C" void kernel_launch(void* const* d_in, const int* in_sizes, int n_in,
                              void* d_out, int out_size) {
    const float* x    = (const float*)d_in[0];
    const float* grid = (const float*)d_in[1];
    const float* w1b  = (const float*)d_in[2];  // (D_FF, D_MODEL)
    const float* w1s  = (const float*)d_in[3];  // (D_FF, D_MODEL, 8) -> (D_FF, 4096) K-major
    const float* w2b  = (const float*)d_in[4];  // (D_MODEL, D_FF)
    const float* w2s  = (const float*)d_in[5];  // (D_MODEL, D_FF, 8) -> (D_MODEL, 16384)
    float* out = (float*)d_out;

    const int ntok = in_sizes[0] / D_MODEL;     // 4096

    float *S1, *B1, *H, *S2, *B2;
    cudaGetSymbolAddress((void**)&S1, g_S1);
    cudaGetSymbolAddress((void**)&B1, g_B1);
    cudaGetSymbolAddress((void**)&H,  g_H);
    cudaGetSymbolAddress((void**)&S2, g_S2);
    cudaGetSymbolAddress((void**)&B2, g_B2);

    // ---- layer 1 ----
    const int tot1 = ntok * D_MODEL;
    expand_kernel<<<(tot1 + 255) / 256, 256>>>(x, grid, S1, B1, tot1);

    dim3 grid1(D_FF / BN, ntok / BM);
    gemm_tn_kernel<<<grid1, 256>>>(S1, w1b, H, ntok, D_FF, D_MODEL, 0);
    gemm_tn_kernel<<<grid1, 256>>>(B1, w1s, H, ntok, D_FF, D_MODEL * GKN, 1);

    // ---- layer 2 ----
    const int tot2 = ntok * D_FF;
    expand_kernel<<<(tot2 + 255) / 256, 256>>>(H, grid, S2, B2, tot2);

    dim3 grid2(D_MODEL / BN, ntok / BM);
    gemm_tn_kernel<<<grid2, 256>>>(S2, w2b, out, ntok, D_MODEL, D_FF, 0);
    gemm_tn_kernel<<<grid2, 256>>>(B2, w2s, out, ntok, D_MODEL, D_FF * GKN, 1);
}

// round 3
// speedup vs baseline: 4.0856x; 4.0856x over previous
#include <cuda_runtime.h>
#include <cuda_bf16.h>
#include <math.h>
#include <stdint.h>

#define D_MODEL 512
#define D_FF    2048
#define GKN     8
#define NTOK    4096

// ---------------------------------------------------------------------------
// Scratch (device globals; runtime allocation forbidden)
// ---------------------------------------------------------------------------
__device__ __nv_bfloat16 g_S1h[(size_t)NTOK * D_MODEL];
__device__ __nv_bfloat16 g_S1l[(size_t)NTOK * D_MODEL];
__device__ __nv_bfloat16 g_B1 [(size_t)NTOK * D_MODEL * GKN];
__device__ float         g_H  [(size_t)NTOK * D_FF];
__device__ __nv_bfloat16 g_S2h[(size_t)NTOK * D_FF];
__device__ __nv_bfloat16 g_S2l[(size_t)NTOK * D_FF];
__device__ __nv_bfloat16 g_B2 [(size_t)NTOK * D_FF * GKN];

__device__ __nv_bfloat16 g_W1bh[(size_t)D_FF * D_MODEL];
__device__ __nv_bfloat16 g_W1bl[(size_t)D_FF * D_MODEL];
__device__ __nv_bfloat16 g_W1s [(size_t)D_FF * D_MODEL * GKN];
__device__ __nv_bfloat16 g_W2bh[(size_t)D_MODEL * D_FF];
__device__ __nv_bfloat16 g_W2bl[(size_t)D_MODEL * D_FF];
__device__ __nv_bfloat16 g_W2s [(size_t)D_MODEL * D_FF * GKN];

// ---------------------------------------------------------------------------
// PTX helpers (arch-agnostic: work on .target sm_103)
// ---------------------------------------------------------------------------
__device__ __forceinline__ uint32_t cvta_smem(const void* p) {
    uint32_t a;
    asm("{ .reg .u64 t; cvta.to.shared.u64 t, %1; cvt.u32.u64 %0, t; }" : "=r"(a) : "l"(p));
    return a;
}
__device__ __forceinline__ void cp16(uint32_t s, const void* g) {
    asm volatile("cp.async.cg.shared.global [%0], [%1], 16;" :: "r"(s), "l"(g));
}
__device__ __forceinline__ void cp_commit() {
    asm volatile("cp.async.commit_group;" ::: "memory");
}
template <int N>
__device__ __forceinline__ void cp_wait() {
    asm volatile("cp.async.wait_group %0;" :: "n"(N) : "memory");
}
__device__ __forceinline__ void ldmx4(uint32_t* r, uint32_t a) {
    asm volatile("ldmatrix.sync.aligned.m8n8.x4.shared.b16 {%0,%1,%2,%3}, [%4];"
                 : "=r"(r[0]), "=r"(r[1]), "=r"(r[2]), "=r"(r[3]) : "r"(a));
}
__device__ __forceinline__ void mma16816(float* d, const uint32_t* a, uint32_t b0, uint32_t b1) {
    asm volatile(
        "mma.sync.aligned.m16n8k16.row.col.f32.bf16.bf16.f32 "
        "{%0,%1,%2,%3}, {%4,%5,%6,%7}, {%8,%9}, {%0,%1,%2,%3};"
        : "+f"(d[0]), "+f"(d[1]), "+f"(d[2]), "+f"(d[3])
        : "r"(a[0]), "r"(a[1]), "r"(a[2]), "r"(a[3]), "r"(b0), "r"(b1));
}

// ---------------------------------------------------------------------------
// Expansion: silu (bf16 hi/lo) + 8 cubic B-spline bases (bf16).
// ---------------------------------------------------------------------------
__global__ void expand_kernel(const float* __restrict__ x,
                              const float* __restrict__ grid,
                              __nv_bfloat16* __restrict__ Sh,
                              __nv_bfloat16* __restrict__ Sl,
                              __nv_bfloat16* __restrict__ Bs,
                              int total) {
    int idx = blockIdx.x * blockDim.x + threadIdx.x;
    if (idx >= total) return;

    float v = x[idx];
    float s = v * __fdividef(1.0f, 1.0f + __expf(-v));
    __nv_bfloat16 sh = __float2bfloat16(s);
    Sh[idx] = sh;
    Sl[idx] = __float2bfloat16(s - __bfloat162float(sh));

    float t[12];
#pragma unroll
    for (int j = 0; j < 12; j++) t[j] = __ldg(grid + j);
    float ih = __fdividef(1.0f, t[1] - t[0]);

    float b[11];
#pragma unroll
    for (int j = 0; j < 11; j++) b[j] = (v >= t[j] && v < t[j + 1]) ? 1.0f : 0.0f;

    const float w1 = ih, w2 = ih * 0.5f, w3 = ih * (1.0f / 3.0f);
#pragma unroll
    for (int i = 0; i < 10; i++)
        b[i] = ((v - t[i]) * b[i] + (t[i + 2] - v) * b[i + 1]) * w1;
#pragma unroll
    for (int i = 0; i < 9; i++)
        b[i] = ((v - t[i]) * b[i] + (t[i + 3] - v) * b[i + 1]) * w2;
#pragma unroll
    for (int i = 0; i < 8; i++)
        b[i] = ((v - t[i]) * b[i] + (t[i + 4] - v) * b[i + 1]) * w3;

    __nv_bfloat162 p0 = __floats2bfloat162_rn(b[0], b[1]);
    __nv_bfloat162 p1 = __floats2bfloat162_rn(b[2], b[3]);
    __nv_bfloat162 p2 = __floats2bfloat162_rn(b[4], b[5]);
    __nv_bfloat162 p3 = __floats2bfloat162_rn(b[6], b[7]);
    uint4 pk;
    pk.x = *(uint32_t*)&p0; pk.y = *(uint32_t*)&p1;
    pk.z = *(uint32_t*)&p2; pk.w = *(uint32_t*)&p3;
    *(uint4*)(Bs + (size_t)idx * 8) = pk;
}

// ---------------------------------------------------------------------------
// Weight conversion
// ---------------------------------------------------------------------------
__global__ void split_w_kernel(const float* __restrict__ w,
                               __nv_bfloat16* __restrict__ hi,
                               __nv_bfloat16* __restrict__ lo, int n4) {
    int i = blockIdx.x * blockDim.x + threadIdx.x;
    if (i >= n4) return;
    float4 v = ((const float4*)w)[i];
    __nv_bfloat16 h0 = __float2bfloat16(v.x), h1 = __float2bfloat16(v.y);
    __nv_bfloat16 h2 = __float2bfloat16(v.z), h3 = __float2bfloat16(v.w);
    ((__nv_bfloat162*)hi)[2 * i]     = __halves2bfloat162(h0, h1);
    ((__nv_bfloat162*)hi)[2 * i + 1] = __halves2bfloat162(h2, h3);
    ((__nv_bfloat162*)lo)[2 * i]     = __floats2bfloat162_rn(v.x - __bfloat162float(h0), v.y - __bfloat162float(h1));
    ((__nv_bfloat162*)lo)[2 * i + 1] = __floats2bfloat162_rn(v.z - __bfloat162float(h2), v.w - __bfloat162float(h3));
}

__global__ void conv_w_kernel(const float* __restrict__ w,
                              __nv_bfloat16* __restrict__ hi, int n4) {
    int i = blockIdx.x * blockDim.x + threadIdx.x;
    if (i >= n4) return;
    float4 v = ((const float4*)w)[i];
    ((__nv_bfloat162*)hi)[2 * i]     = __floats2bfloat162_rn(v.x, v.y);
    ((__nv_bfloat162*)hi)[2 * i + 1] = __floats2bfloat162_rn(v.z, v.w);
}

// ---------------------------------------------------------------------------
// bf16 mma.sync GEMM: C(M,Nout) (+)= A(M,K) * B(Nout,K)^T, fp32 accumulate.
// BM=BN=128, BK=32, 8 warps (2x4), warp tile 64x32, 3-stage cp.async pipeline.
// SMEM rows padded to 40 bf16 (80B): conflict-free for cp.async + ldmatrix.
// M,Nout multiples of 128; K multiple of 32.
// ---------------------------------------------------------------------------
#define BM 128
#define BN 128
#define BKK 32
#define STAGES 3
#define LDT 40            // padded row length in bf16 elems
#define TILE_E (128 * LDT)  // elems per tile per stage

__global__ void __launch_bounds__(256)
gemm_mma(const __nv_bfloat16* __restrict__ A, const __nv_bfloat16* __restrict__ B,
         float* __restrict__ C, int M, int Nout, int K, int accumulate) {
    extern __shared__ __nv_bfloat16 sm[];
    // layout: [STAGES][A(128xLDT), B(128xLDT)]
    const uint32_t sm_base = cvta_smem(sm);

    const int tid = threadIdx.x;
    const int lane = tid & 31;
    const int wid = tid >> 5;
    const int wm = wid >> 2;        // 0..1 -> 64-row half
    const int wn = wid & 3;         // 0..3 -> 32-col quarter
    const int m0 = blockIdx.y * BM;
    const int n0 = blockIdx.x * BN;

    const __nv_bfloat16* Ag = A + (size_t)m0 * K;
    const __nv_bfloat16* Bg = B + (size_t)n0 * K;

    // cp.async mapping: 16B per thread; row=tid/4, col chunk=(tid&3)*8 elems
    const int lrow = tid >> 2;
    const int lcol = (tid & 3) * 8;

    const int nk = K / BKK;

    auto stage_load = [&](int ks) {
        const int buf = ks % STAGES;
        const size_t koff = (size_t)ks * BKK + lcol;
        const uint32_t abase = sm_base + (uint32_t)(buf * 2 * TILE_E) * 2;
        const uint32_t bbase = abase + (uint32_t)TILE_E * 2;
#pragma unroll
        for (int r = 0; r < BM; r += 64) {
            cp16(abase + (uint32_t)((lrow + r) * LDT + lcol) * 2,
                 Ag + (size_t)(lrow + r) * K + koff);
        }
#pragma unroll
        for (int r = 0; r < BN; r += 64) {
            cp16(bbase + (uint32_t)((lrow + r) * LDT + lcol) * 2,
                 Bg + (size_t)(lrow + r) * K + koff);
        }
        cp_commit();
    };

    float acc[4][4][4];
#pragma unroll
    for (int i = 0; i < 4; i++)
#pragma unroll
        for (int j = 0; j < 4; j++)
#pragma unroll
            for (int e = 0; e < 4; e++) acc[i][j][e] = 0.0f;

    // ldmatrix per-thread address components
    const int lm_row = lane & 15;       // row within 16
    const int lm_koff = (lane >> 4) * 8; // 0 or 8 elems

    stage_load(0);
    stage_load(1);

    for (int ks = 0; ks < nk; ks++) {
        cp_wait<STAGES - 2>();
        __syncthreads();
        if (ks + STAGES - 1 < nk) stage_load(ks + STAGES - 1);

        const int buf = ks % STAGES;
        const uint32_t abase = sm_base + (uint32_t)(buf * 2 * TILE_E) * 2;
        const uint32_t bbase = abase + (uint32_t)TILE_E * 2;

#pragma unroll
        for (int kf = 0; kf < 2; kf++) {
            uint32_t afr[4][4];
#pragma unroll
            for (int mi = 0; mi < 4; mi++) {
                uint32_t addr = abase +
                    (uint32_t)((wm * 64 + mi * 16 + lm_row) * LDT + kf * 16 + lm_koff) * 2;
                ldmx4(afr[mi], addr);
            }
            uint32_t bfr[2][4];
#pragma unroll
            for (int nf2 = 0; nf2 < 2; nf2++) {
                uint32_t addr = bbase +
                    (uint32_t)((wn * 32 + nf2 * 16 + lm_row) * LDT + kf * 16 + lm_koff) * 2;
                ldmx4(bfr[nf2], addr);
            }
#pragma unroll
            for (int mi = 0; mi < 4; mi++)
#pragma unroll
                for (int ni = 0; ni < 4; ni++) {
                    const int g = ni >> 1, o = ni & 1;
                    mma16816(acc[mi][ni], afr[mi], bfr[g][o], bfr[g][o + 2]);
                }
        }
        __syncthreads();
    }

    // epilogue
    const int erow = lane >> 2;
    const int ecol = (lane & 3) * 2;
#pragma unroll
    for (int mi = 0; mi < 4; mi++) {
#pragma unroll
        for (int ni = 0; ni < 4; ni++) {
            const int row = m0 + wm * 64 + mi * 16 + erow;
            const int col = n0 + wn * 32 + ni * 8 + ecol;
            float* p0 = C + (size_t)row * Nout + col;
            float* p1 = C + (size_t)(row + 8) * Nout + col;
            float2 v0 = make_float2(acc[mi][ni][0], acc[mi][ni][1]);
            float2 v1 = make_float2(acc[mi][ni][2], acc[mi][ni][3]);
            if (accumulate) {
                float2 o0 = *(const float2*)p0;
                float2 o1 = *(const float2*)p1;
                v0.x += o0.x; v0.y += o0.y;
                v1.x += o1.x; v1.y += o1.y;
            }
            *(float2*)p0 = v0;
            *(float2*)p1 = v1;
        }
    }
}

// ---------------------------------------------------------------------------
// Launch
// ---------------------------------------------------------------------------
extern "C" void kernel_launch(void* const* d_in, const int* in_sizes, int n_in,
                              void* d_out, int out_size) {
    const float* x    = (const float*)d_in[0];
    const float* grid = (const float*)d_in[1];
    const float* w1b  = (const float*)d_in[2];
    const float* w1s  = (const float*)d_in[3];
    const float* w2b  = (const float*)d_in[4];
    const float* w2s  = (const float*)d_in[5];
    float* out = (float*)d_out;

    const int ntok = in_sizes[0] / D_MODEL;  // 4096

    __nv_bfloat16 *S1h, *S1l, *B1, *S2h, *S2l, *B2;
    __nv_bfloat16 *W1bh, *W1bl, *W1s, *W2bh, *W2bl, *W2s;
    float* H;
    cudaGetSymbolAddress((void**)&S1h, g_S1h);
    cudaGetSymbolAddress((void**)&S1l, g_S1l);
    cudaGetSymbolAddress((void**)&B1,  g_B1);
    cudaGetSymbolAddress((void**)&H,   g_H);
    cudaGetSymbolAddress((void**)&S2h, g_S2h);
    cudaGetSymbolAddress((void**)&S2l, g_S2l);
    cudaGetSymbolAddress((void**)&B2,  g_B2);
    cudaGetSymbolAddress((void**)&W1bh, g_W1bh);
    cudaGetSymbolAddress((void**)&W1bl, g_W1bl);
    cudaGetSymbolAddress((void**)&W1s,  g_W1s);
    cudaGetSymbolAddress((void**)&W2bh, g_W2bh);
    cudaGetSymbolAddress((void**)&W2bl, g_W2bl);
    cudaGetSymbolAddress((void**)&W2s,  g_W2s);

    const int smem_bytes = STAGES * 2 * TILE_E * 2;  // 61440
    cudaFuncSetAttribute(gemm_mma, cudaFuncAttributeMaxDynamicSharedMemorySize, smem_bytes);

    // weight conversion
    {
        int n;
        n = D_FF * D_MODEL / 4;
        split_w_kernel<<<(n + 255) / 256, 256>>>(w1b, W1bh, W1bl, n);
        n = D_MODEL * D_FF / 4;
        split_w_kernel<<<(n + 255) / 256, 256>>>(w2b, W2bh, W2bl, n);
        n = D_FF * D_MODEL * GKN / 4;
        conv_w_kernel<<<(n + 255) / 256, 256>>>(w1s, W1s, n);
        n = D_MODEL * D_FF * GKN / 4;
        conv_w_kernel<<<(n + 255) / 256, 256>>>(w2s, W2s, n);
    }

    // ---- layer 1 ----
    const int tot1 = ntok * D_MODEL;
    expand_kernel<<<(tot1 + 255) / 256, 256>>>(x, grid, S1h, S1l, B1, tot1);

    dim3 grid1(D_FF / BN, ntok / BM);
    gemm_mma<<<grid1, 256, smem_bytes>>>(S1h, W1bh, H, ntok, D_FF, D_MODEL, 0);
    gemm_mma<<<grid1, 256, smem_bytes>>>(S1h, W1bl, H, ntok, D_FF, D_MODEL, 1);
    gemm_mma<<<grid1, 256, smem_bytes>>>(S1l, W1bh, H, ntok, D_FF, D_MODEL, 1);
    gemm_mma<<<grid1, 256, smem_bytes>>>(B1,  W1s,  H, ntok, D_FF, D_MODEL * GKN, 1);

    // ---- layer 2 ----
    const int tot2 = ntok * D_FF;
    expand_kernel<<<(tot2 + 255) / 256, 256>>>(H, grid, S2h, S2l, B2, tot2);

    dim3 grid2(D_MODEL / BN, ntok / BM);
    gemm_mma<<<grid2, 256, smem_bytes>>>(S2h, W2bh, out, ntok, D_MODEL, D_FF, 0);
    gemm_mma<<<grid2, 256, smem_bytes>>>(S2h, W2bl, out, ntok, D_MODEL, D_FF, 1);
    gemm_mma<<<grid2, 256, smem_bytes>>>(S2l, W2bh, out, ntok, D_MODEL, D_FF, 1);
    gemm_mma<<<grid2, 256, smem_bytes>>>(B2,  W2s,  out, ntok, D_MODEL, D_FF * GKN, 1);
}

// round 4
// speedup vs baseline: 4.7279x; 1.1572x over previous
#include <cuda_runtime.h>
#include <cuda_bf16.h>
#include <math.h>
#include <stdint.h>

#define D_MODEL 512
#define D_FF    2048
#define GKN     8
#define NTOK    4096

// K-concat layouts:
//  layer1 activations: [bases(4096) | Sh(512) | Sh(512) | Sl(512)]  strideK=5632
//  layer1 weights:     [Ws  (4096)  | Wbh(512)| Wbl(512)| Wbh(512)]
//  layer2 activations: [bases(16384)| Sh(2048)| Sh(2048)| Sl(2048)] strideK=22528
#define K1P (D_MODEL * GKN + 3 * D_MODEL)   // 5632
#define K2P (D_FF * GKN + 3 * D_FF)         // 22528

// ---------------------------------------------------------------------------
// Scratch (device globals; runtime allocation forbidden)
// ---------------------------------------------------------------------------
__device__ __nv_bfloat16 g_A1[(size_t)NTOK * K1P];     //  46 MB
__device__ __nv_bfloat16 g_A2[(size_t)NTOK * K2P];     // 185 MB
__device__ __nv_bfloat16 g_W1[(size_t)D_FF * K1P];     //  23 MB
__device__ __nv_bfloat16 g_W2[(size_t)D_MODEL * K2P];  //  23 MB
__device__ float         g_H [(size_t)NTOK * D_FF];    //  34 MB

// ---------------------------------------------------------------------------
// PTX helpers (arch-agnostic on .target sm_103)
// ---------------------------------------------------------------------------
__device__ __forceinline__ uint32_t cvta_smem(const void* p) {
    uint32_t a;
    asm("{ .reg .u64 t; cvta.to.shared.u64 t, %1; cvt.u32.u64 %0, t; }" : "=r"(a) : "l"(p));
    return a;
}
__device__ __forceinline__ void cp16(uint32_t s, const void* g) {
    asm volatile("cp.async.cg.shared.global [%0], [%1], 16;" :: "r"(s), "l"(g));
}
__device__ __forceinline__ void cp_commit() {
    asm volatile("cp.async.commit_group;" ::: "memory");
}
template <int N>
__device__ __forceinline__ void cp_wait() {
    asm volatile("cp.async.wait_group %0;" :: "n"(N) : "memory");
}
__device__ __forceinline__ void ldmx4(uint32_t* r, uint32_t a) {
    asm volatile("ldmatrix.sync.aligned.m8n8.x4.shared.b16 {%0,%1,%2,%3}, [%4];"
                 : "=r"(r[0]), "=r"(r[1]), "=r"(r[2]), "=r"(r[3]) : "r"(a));
}
__device__ __forceinline__ void mma16816(float* d, const uint32_t* a, uint32_t b0, uint32_t b1) {
    asm volatile(
        "mma.sync.aligned.m16n8k16.row.col.f32.bf16.bf16.f32 "
        "{%0,%1,%2,%3}, {%4,%5,%6,%7}, {%8,%9}, {%0,%1,%2,%3};"
        : "+f"(d[0]), "+f"(d[1]), "+f"(d[2]), "+f"(d[3])
        : "r"(a[0]), "r"(a[1]), "r"(a[2]), "r"(a[3]), "r"(b0), "r"(b1));
}

// ---------------------------------------------------------------------------
// Expansion into packed K-concat activation buffer.
//  pA[row][i*8 .. i*8+7] = bases; [off+i]=Sh; [off+IN+i]=Sh; [off+2IN+i]=Sl
// ---------------------------------------------------------------------------
__global__ void expand_pack(const float* __restrict__ x,
                            const float* __restrict__ grid,
                            __nv_bfloat16* __restrict__ pA,
                            int total, int in_log2, int strideK) {
    int idx = blockIdx.x * blockDim.x + threadIdx.x;
    if (idx >= total) return;
    const int IN = 1 << in_log2;
    const int row = idx >> in_log2;
    const int i = idx & (IN - 1);

    float v = x[idx];
    float s = v * __fdividef(1.0f, 1.0f + __expf(-v));
    __nv_bfloat16 sh = __float2bfloat16(s);
    __nv_bfloat16 sl = __float2bfloat16(s - __bfloat162float(sh));

    float t[12];
#pragma unroll
    for (int j = 0; j < 12; j++) t[j] = __ldg(grid + j);
    float ih = __fdividef(1.0f, t[1] - t[0]);

    float b[11];
#pragma unroll
    for (int j = 0; j < 11; j++) b[j] = (v >= t[j] && v < t[j + 1]) ? 1.0f : 0.0f;

    const float w1 = ih, w2 = ih * 0.5f, w3 = ih * (1.0f / 3.0f);
#pragma unroll
    for (int q = 0; q < 10; q++)
        b[q] = ((v - t[q]) * b[q] + (t[q + 2] - v) * b[q + 1]) * w1;
#pragma unroll
    for (int q = 0; q < 9; q++)
        b[q] = ((v - t[q]) * b[q] + (t[q + 3] - v) * b[q + 1]) * w2;
#pragma unroll
    for (int q = 0; q < 8; q++)
        b[q] = ((v - t[q]) * b[q] + (t[q + 4] - v) * b[q + 1]) * w3;

    __nv_bfloat162 p0 = __floats2bfloat162_rn(b[0], b[1]);
    __nv_bfloat162 p1 = __floats2bfloat162_rn(b[2], b[3]);
    __nv_bfloat162 p2 = __floats2bfloat162_rn(b[4], b[5]);
    __nv_bfloat162 p3 = __floats2bfloat162_rn(b[6], b[7]);
    uint4 pk;
    pk.x = *(uint32_t*)&p0; pk.y = *(uint32_t*)&p1;
    pk.z = *(uint32_t*)&p2; pk.w = *(uint32_t*)&p3;

    __nv_bfloat16* rowp = pA + (size_t)row * strideK;
    *(uint4*)(rowp + i * 8) = pk;
    const int off = IN * 8;
    rowp[off + i]          = sh;
    rowp[off + IN + i]     = sh;
    rowp[off + 2 * IN + i] = sl;
}

// ---------------------------------------------------------------------------
// Weight packing into K-concat layout: [Ws | Wbh | Wbl | Wbh]
// ---------------------------------------------------------------------------
__global__ void pack_w(const float* __restrict__ wb,
                       const float* __restrict__ ws,
                       __nv_bfloat16* __restrict__ pW,
                       int total, int in_log2, int strideK) {
    int idx = blockIdx.x * blockDim.x + threadIdx.x;
    if (idx >= total) return;
    const int IN = 1 << in_log2;
    const int o = idx >> in_log2;
    const int i = idx & (IN - 1);

    float base = wb[idx];
    __nv_bfloat16 hi = __float2bfloat16(base);
    __nv_bfloat16 lo = __float2bfloat16(base - __bfloat162float(hi));

    float4 s0 = ((const float4*)ws)[idx * 2];
    float4 s1 = ((const float4*)ws)[idx * 2 + 1];
    __nv_bfloat162 p0 = __floats2bfloat162_rn(s0.x, s0.y);
    __nv_bfloat162 p1 = __floats2bfloat162_rn(s0.z, s0.w);
    __nv_bfloat162 p2 = __floats2bfloat162_rn(s1.x, s1.y);
    __nv_bfloat162 p3 = __floats2bfloat162_rn(s1.z, s1.w);
    uint4 pk;
    pk.x = *(uint32_t*)&p0; pk.y = *(uint32_t*)&p1;
    pk.z = *(uint32_t*)&p2; pk.w = *(uint32_t*)&p3;

    __nv_bfloat16* rowp = pW + (size_t)o * strideK;
    *(uint4*)(rowp + i * 8) = pk;
    const int off = IN * 8;
    rowp[off + i]          = hi;
    rowp[off + IN + i]     = lo;
    rowp[off + 2 * IN + i] = hi;
}

// ---------------------------------------------------------------------------
// bf16 mma.sync GEMM: C(M,Nout) = A(M,K) * B(Nout,K)^T, fp32 accumulate.
// BM=128, BN_ in {128,64}. 8 warps (2 x 4); warp tile 64 x (NI*8).
// BK=32, 3-stage cp.async pipeline, padded SMEM rows (40 bf16).
// ---------------------------------------------------------------------------
#define BM 128
#define BKK 32
#define STAGES 3
#define LDT 40

template <int BN_, int NI>
__global__ void __launch_bounds__(256, 2)
gemm_mma(const __nv_bfloat16* __restrict__ A, const __nv_bfloat16* __restrict__ B,
         float* __restrict__ C, int M, int Nout, int K) {
    constexpr int TILE_A = BM * LDT;
    constexpr int TILE_B = BN_ * LDT;
    extern __shared__ __nv_bfloat16 sm[];
    const uint32_t sm_base = cvta_smem(sm);

    const int tid = threadIdx.x;
    const int lane = tid & 31;
    const int wid = tid >> 5;
    const int wm = wid >> 2;        // 0..1 -> 64-row half
    const int wn = wid & 3;         // 0..3 -> (NI*8)-col group
    const int m0 = blockIdx.y * BM;
    const int n0 = blockIdx.x * BN_;

    const __nv_bfloat16* Ag = A + (size_t)m0 * K;
    const __nv_bfloat16* Bg = B + (size_t)n0 * K;

    const int lrow = tid >> 2;
    const int lcol = (tid & 3) * 8;

    const int nk = K / BKK;

    auto stage_load = [&](int ks) {
        const int buf = ks % STAGES;
        const size_t koff = (size_t)ks * BKK + lcol;
        const uint32_t abase = sm_base + (uint32_t)(buf * (TILE_A + TILE_B)) * 2;
        const uint32_t bbase = abase + (uint32_t)TILE_A * 2;
#pragma unroll
        for (int r = 0; r < BM; r += 64)
            cp16(abase + (uint32_t)((lrow + r) * LDT + lcol) * 2,
                 Ag + (size_t)(lrow + r) * K + koff);
#pragma unroll
        for (int r = 0; r < BN_; r += 64)
            cp16(bbase + (uint32_t)((lrow + r) * LDT + lcol) * 2,
                 Bg + (size_t)(lrow + r) * K + koff);
        cp_commit();
    };

    float acc[4][NI][4];
#pragma unroll
    for (int i = 0; i < 4; i++)
#pragma unroll
        for (int j = 0; j < NI; j++)
#pragma unroll
            for (int e = 0; e < 4; e++) acc[i][j][e] = 0.0f;

    const int lm_row = lane & 15;
    const int lm_koff = (lane >> 4) * 8;

    stage_load(0);
    stage_load(1);

    for (int ks = 0; ks < nk; ks++) {
        cp_wait<STAGES - 2>();
        __syncthreads();
        if (ks + STAGES - 1 < nk) stage_load(ks + STAGES - 1);

        const int buf = ks % STAGES;
        const uint32_t abase = sm_base + (uint32_t)(buf * (TILE_A + TILE_B)) * 2;
        const uint32_t bbase = abase + (uint32_t)TILE_A * 2;

#pragma unroll
        for (int kf = 0; kf < 2; kf++) {
            uint32_t afr[4][4];
#pragma unroll
            for (int mi = 0; mi < 4; mi++) {
                uint32_t addr = abase +
                    (uint32_t)((wm * 64 + mi * 16 + lm_row) * LDT + kf * 16 + lm_koff) * 2;
                ldmx4(afr[mi], addr);
            }
            uint32_t bfr[NI / 2][4];
#pragma unroll
            for (int g = 0; g < NI / 2; g++) {
                uint32_t addr = bbase +
                    (uint32_t)((wn * (NI * 8) + g * 16 + lm_row) * LDT + kf * 16 + lm_koff) * 2;
                ldmx4(bfr[g], addr);
            }
#pragma unroll
            for (int mi = 0; mi < 4; mi++)
#pragma unroll
                for (int ni = 0; ni < NI; ni++) {
                    const int g = ni >> 1, o = ni & 1;
                    mma16816(acc[mi][ni], afr[mi], bfr[g][o], bfr[g][o + 2]);
                }
        }
        __syncthreads();
    }

    // epilogue (no accumulate: single fused GEMM per layer)
    const int erow = lane >> 2;
    const int ecol = (lane & 3) * 2;
#pragma unroll
    for (int mi = 0; mi < 4; mi++) {
#pragma unroll
        for (int ni = 0; ni < NI; ni++) {
            const int row = m0 + wm * 64 + mi * 16 + erow;
            const int col = n0 + wn * (NI * 8) + ni * 8 + ecol;
            float* p0 = C + (size_t)row * Nout + col;
            float* p1 = C + (size_t)(row + 8) * Nout + col;
            *(float2*)p0 = make_float2(acc[mi][ni][0], acc[mi][ni][1]);
            *(float2*)p1 = make_float2(acc[mi][ni][2], acc[mi][ni][3]);
        }
    }
}

// ---------------------------------------------------------------------------
// Launch
// ---------------------------------------------------------------------------
extern "C" void kernel_launch(void* const* d_in, const int* in_sizes, int n_in,
                              void* d_out, int out_size) {
    const float* x    = (const float*)d_in[0];
    const float* grid = (const float*)d_in[1];
    const float* w1b  = (const float*)d_in[2];
    const float* w1s  = (const float*)d_in[3];
    const float* w2b  = (const float*)d_in[4];
    const float* w2s  = (const float*)d_in[5];
    float* out = (float*)d_out;

    const int ntok = in_sizes[0] / D_MODEL;  // 4096

    __nv_bfloat16 *A1, *A2, *W1, *W2;
    float* H;
    cudaGetSymbolAddress((void**)&A1, g_A1);
    cudaGetSymbolAddress((void**)&A2, g_A2);
    cudaGetSymbolAddress((void**)&W1, g_W1);
    cudaGetSymbolAddress((void**)&W2, g_W2);
    cudaGetSymbolAddress((void**)&H,  g_H);

    const int smem1 = STAGES * (BM + 128) * LDT * 2;  // 61440
    const int smem2 = STAGES * (BM + 64) * LDT * 2;   // 46080
    cudaFuncSetAttribute(gemm_mma<128, 4>, cudaFuncAttributeMaxDynamicSharedMemorySize, smem1);
    cudaFuncSetAttribute(gemm_mma<64, 2>,  cudaFuncAttributeMaxDynamicSharedMemorySize, smem2);

    // pack weights into K-concat layout
    {
        int n1 = D_FF * D_MODEL;   // layer1: in=512 (log2=9)
        pack_w<<<(n1 + 255) / 256, 256>>>(w1b, w1s, W1, n1, 9, K1P);
        int n2 = D_MODEL * D_FF;   // layer2: in=2048 (log2=11)
        pack_w<<<(n2 + 255) / 256, 256>>>(w2b, w2s, W2, n2, 11, K2P);
    }

    // ---- layer 1 ----
    const int tot1 = ntok * D_MODEL;
    expand_pack<<<(tot1 + 255) / 256, 256>>>(x, grid, A1, tot1, 9, K1P);

    dim3 grid1(D_FF / 128, ntok / BM);
    gemm_mma<128, 4><<<grid1, 256, smem1>>>(A1, W1, H, ntok, D_FF, K1P);

    // ---- layer 2 ----
    const int tot2 = ntok * D_FF;
    expand_pack<<<(tot2 + 255) / 256, 256>>>(H, grid, A2, tot2, 11, K2P);

    dim3 grid2(D_MODEL / 64, ntok / BM);
    gemm_mma<64, 2><<<grid2, 256, smem2>>>(A2, W2, out, ntok, D_MODEL, K2P);
}

// round 5
// speedup vs baseline: 5.1567x; 1.0907x over previous
#include <cuda_runtime.h>
#include <cuda_bf16.h>
#include <math.h>
#include <stdint.h>

#define D_MODEL 512
#define D_FF    2048
#define GKN     8
#define NTOK    4096

// K-concat layouts:
//  layer1 activations: [bases(4096) | Sh(512) | Sh(512) | Sl(512)]  strideK=5632
//  layer1 weights:     [Ws  (4096)  | Wbh(512)| Wbl(512)| Wbh(512)]
//  layer2 activations: [bases(16384)| Sh(2048)| Sh(2048)| Sl(2048)] strideK=22528
#define K1P (D_MODEL * GKN + 3 * D_MODEL)   // 5632
#define K2P (D_FF * GKN + 3 * D_FF)         // 22528

__device__ __nv_bfloat16 g_A1[(size_t)NTOK * K1P];
__device__ __nv_bfloat16 g_A2[(size_t)NTOK * K2P];
__device__ __nv_bfloat16 g_W1[(size_t)D_FF * K1P];
__device__ __nv_bfloat16 g_W2[(size_t)D_MODEL * K2P];
__device__ float         g_H [(size_t)NTOK * D_FF];

// ---------------------------------------------------------------------------
// PTX helpers (arch-agnostic on .target sm_103)
// ---------------------------------------------------------------------------
__device__ __forceinline__ uint32_t cvta_smem(const void* p) {
    uint32_t a;
    asm("{ .reg .u64 t; cvta.to.shared.u64 t, %1; cvt.u32.u64 %0, t; }" : "=r"(a) : "l"(p));
    return a;
}
__device__ __forceinline__ void cp16(uint32_t s, const void* g) {
    asm volatile("cp.async.cg.shared.global [%0], [%1], 16;" :: "r"(s), "l"(g));
}
__device__ __forceinline__ void cp_commit() {
    asm volatile("cp.async.commit_group;" ::: "memory");
}
template <int N>
__device__ __forceinline__ void cp_wait() {
    asm volatile("cp.async.wait_group %0;" :: "n"(N) : "memory");
}
__device__ __forceinline__ void ldmx4(uint32_t* r, uint32_t a) {
    asm volatile("ldmatrix.sync.aligned.m8n8.x4.shared.b16 {%0,%1,%2,%3}, [%4];"
                 : "=r"(r[0]), "=r"(r[1]), "=r"(r[2]), "=r"(r[3]) : "r"(a));
}
__device__ __forceinline__ void mma16816(float* d, const uint32_t* a, uint32_t b0, uint32_t b1) {
    asm volatile(
        "mma.sync.aligned.m16n8k16.row.col.f32.bf16.bf16.f32 "
        "{%0,%1,%2,%3}, {%4,%5,%6,%7}, {%8,%9}, {%0,%1,%2,%3};"
        : "+f"(d[0]), "+f"(d[1]), "+f"(d[2]), "+f"(d[3])
        : "r"(a[0]), "r"(a[1]), "r"(a[2]), "r"(a[3]), "r"(b0), "r"(b1));
}

// ---------------------------------------------------------------------------
// Expansion into packed K-concat activation buffer.
// ---------------------------------------------------------------------------
__global__ void expand_pack(const float* __restrict__ x,
                            const float* __restrict__ grid,
                            __nv_bfloat16* __restrict__ pA,
                            int total, int in_log2, int strideK) {
    int idx = blockIdx.x * blockDim.x + threadIdx.x;
    if (idx >= total) return;
    const int IN = 1 << in_log2;
    const int row = idx >> in_log2;
    const int i = idx & (IN - 1);

    float v = x[idx];
    float s = v * __fdividef(1.0f, 1.0f + __expf(-v));
    __nv_bfloat16 sh = __float2bfloat16(s);
    __nv_bfloat16 sl = __float2bfloat16(s - __bfloat162float(sh));

    float t[12];
#pragma unroll
    for (int j = 0; j < 12; j++) t[j] = __ldg(grid + j);
    float ih = __fdividef(1.0f, t[1] - t[0]);

    float b[11];
#pragma unroll
    for (int j = 0; j < 11; j++) b[j] = (v >= t[j] && v < t[j + 1]) ? 1.0f : 0.0f;

    const float w1 = ih, w2 = ih * 0.5f, w3 = ih * (1.0f / 3.0f);
#pragma unroll
    for (int q = 0; q < 10; q++)
        b[q] = ((v - t[q]) * b[q] + (t[q + 2] - v) * b[q + 1]) * w1;
#pragma unroll
    for (int q = 0; q < 9; q++)
        b[q] = ((v - t[q]) * b[q] + (t[q + 3] - v) * b[q + 1]) * w2;
#pragma unroll
    for (int q = 0; q < 8; q++)
        b[q] = ((v - t[q]) * b[q] + (t[q + 4] - v) * b[q + 1]) * w3;

    __nv_bfloat162 p0 = __floats2bfloat162_rn(b[0], b[1]);
    __nv_bfloat162 p1 = __floats2bfloat162_rn(b[2], b[3]);
    __nv_bfloat162 p2 = __floats2bfloat162_rn(b[4], b[5]);
    __nv_bfloat162 p3 = __floats2bfloat162_rn(b[6], b[7]);
    uint4 pk;
    pk.x = *(uint32_t*)&p0; pk.y = *(uint32_t*)&p1;
    pk.z = *(uint32_t*)&p2; pk.w = *(uint32_t*)&p3;

    __nv_bfloat16* rowp = pA + (size_t)row * strideK;
    *(uint4*)(rowp + i * 8) = pk;
    const int off = IN * 8;
    rowp[off + i]          = sh;
    rowp[off + IN + i]     = sh;
    rowp[off + 2 * IN + i] = sl;
}

// ---------------------------------------------------------------------------
// Weight packing: [Ws | Wbh | Wbl | Wbh]
// ---------------------------------------------------------------------------
__global__ void pack_w(const float* __restrict__ wb,
                       const float* __restrict__ ws,
                       __nv_bfloat16* __restrict__ pW,
                       int total, int in_log2, int strideK) {
    int idx = blockIdx.x * blockDim.x + threadIdx.x;
    if (idx >= total) return;
    const int IN = 1 << in_log2;
    const int o = idx >> in_log2;
    const int i = idx & (IN - 1);

    float base = wb[idx];
    __nv_bfloat16 hi = __float2bfloat16(base);
    __nv_bfloat16 lo = __float2bfloat16(base - __bfloat162float(hi));

    float4 s0 = ((const float4*)ws)[idx * 2];
    float4 s1 = ((const float4*)ws)[idx * 2 + 1];
    __nv_bfloat162 p0 = __floats2bfloat162_rn(s0.x, s0.y);
    __nv_bfloat162 p1 = __floats2bfloat162_rn(s0.z, s0.w);
    __nv_bfloat162 p2 = __floats2bfloat162_rn(s1.x, s1.y);
    __nv_bfloat162 p3 = __floats2bfloat162_rn(s1.z, s1.w);
    uint4 pk;
    pk.x = *(uint32_t*)&p0; pk.y = *(uint32_t*)&p1;
    pk.z = *(uint32_t*)&p2; pk.w = *(uint32_t*)&p3;

    __nv_bfloat16* rowp = pW + (size_t)o * strideK;
    *(uint4*)(rowp + i * 8) = pk;
    const int off = IN * 8;
    rowp[off + i]          = hi;
    rowp[off + IN + i]     = lo;
    rowp[off + 2 * IN + i] = hi;
}

// ---------------------------------------------------------------------------
// bf16 mma.sync GEMM: C(M,Nout) = A(M,K) * B(Nout,K)^T, fp32 accumulate.
// Warp grid WM x WN (8 warps), warp tile (MI*16) x (NI*8).
// BK=64, 3-stage cp.async ring, ONE __syncthreads per K-iter,
// SMEM rows padded to 72 bf16 (144B) -> conflict-free ldmatrix.
// ---------------------------------------------------------------------------
#define BKK 64
#define STAGES 3
#define LDT 72

template <int WM, int WN, int MI, int NI>
__global__ void __launch_bounds__(256, 2)
gemm_mma(const __nv_bfloat16* __restrict__ A, const __nv_bfloat16* __restrict__ B,
         float* __restrict__ C, int Nout, int K) {
    constexpr int BM_ = WM * MI * 16;
    constexpr int BN_ = WN * NI * 8;
    constexpr int TILE_A = BM_ * LDT;
    constexpr int TILE_B = BN_ * LDT;
    extern __shared__ __nv_bfloat16 sm[];
    const uint32_t sm_base = cvta_smem(sm);

    const int tid = threadIdx.x;
    const int lane = tid & 31;
    const int wid = tid >> 5;
    const int wm = wid / WN;
    const int wn = wid % WN;
    const int m0 = blockIdx.y * BM_;
    const int n0 = blockIdx.x * BN_;

    const __nv_bfloat16* Ag = A + (size_t)m0 * K;
    const __nv_bfloat16* Bg = B + (size_t)n0 * K;

    // loader: 8 threads per 64-elem row (16B each); 256 threads = 32 rows/pass
    const int lrow = tid >> 3;
    const int lcol = (tid & 7) * 8;

    const int nk = K / BKK;

    auto stage_load = [&](int ks) {
        const int buf = ks % STAGES;
        const size_t koff = (size_t)ks * BKK + lcol;
        const uint32_t abase = sm_base + (uint32_t)(buf * (TILE_A + TILE_B)) * 2;
        const uint32_t bbase = abase + (uint32_t)TILE_A * 2;
#pragma unroll
        for (int r = 0; r < BM_; r += 32)
            cp16(abase + (uint32_t)((lrow + r) * LDT + lcol) * 2,
                 Ag + (size_t)(lrow + r) * K + koff);
#pragma unroll
        for (int r = 0; r < BN_; r += 32)
            cp16(bbase + (uint32_t)((lrow + r) * LDT + lcol) * 2,
                 Bg + (size_t)(lrow + r) * K + koff);
        cp_commit();
    };

    float acc[MI][NI][4];
#pragma unroll
    for (int i = 0; i < MI; i++)
#pragma unroll
        for (int j = 0; j < NI; j++)
#pragma unroll
            for (int e = 0; e < 4; e++) acc[i][j][e] = 0.0f;

    const int lm_row = lane & 15;
    const int lm_koff = (lane >> 4) * 8;

    stage_load(0);
    stage_load(1);

    for (int ks = 0; ks < nk; ks++) {
        if (ks + 1 < nk) cp_wait<1>(); else cp_wait<0>();
        __syncthreads();
        // issue 2-ahead load; its buffer was last read at iter ks-1,
        // and every warp passed this iteration's barrier after finishing it.
        if (ks + 2 < nk) stage_load(ks + 2);

        const int buf = ks % STAGES;
        const uint32_t abase = sm_base + (uint32_t)(buf * (TILE_A + TILE_B)) * 2;
        const uint32_t bbase = abase + (uint32_t)TILE_A * 2;

#pragma unroll
        for (int kf = 0; kf < 4; kf++) {
            uint32_t afr[MI][4];
#pragma unroll
            for (int mi = 0; mi < MI; mi++) {
                uint32_t addr = abase +
                    (uint32_t)((wm * MI * 16 + mi * 16 + lm_row) * LDT + kf * 16 + lm_koff) * 2;
                ldmx4(afr[mi], addr);
            }
            uint32_t bfr[NI / 2][4];
#pragma unroll
            for (int g = 0; g < NI / 2; g++) {
                uint32_t addr = bbase +
                    (uint32_t)((wn * NI * 8 + g * 16 + lm_row) * LDT + kf * 16 + lm_koff) * 2;
                ldmx4(bfr[g], addr);
            }
#pragma unroll
            for (int mi = 0; mi < MI; mi++)
#pragma unroll
                for (int ni = 0; ni < NI; ni++) {
                    const int g = ni >> 1, o = ni & 1;
                    mma16816(acc[mi][ni], afr[mi], bfr[g][o], bfr[g][o + 2]);
                }
        }
    }

    // epilogue
    const int erow = lane >> 2;
    const int ecol = (lane & 3) * 2;
#pragma unroll
    for (int mi = 0; mi < MI; mi++) {
#pragma unroll
        for (int ni = 0; ni < NI; ni++) {
            const int row = m0 + wm * MI * 16 + mi * 16 + erow;
            const int col = n0 + wn * NI * 8 + ni * 8 + ecol;
            float* p0 = C + (size_t)row * Nout + col;
            float* p1 = C + (size_t)(row + 8) * Nout + col;
            *(float2*)p0 = make_float2(acc[mi][ni][0], acc[mi][ni][1]);
            *(float2*)p1 = make_float2(acc[mi][ni][2], acc[mi][ni][3]);
        }
    }
}

// ---------------------------------------------------------------------------
// Launch
// ---------------------------------------------------------------------------
extern "C" void kernel_launch(void* const* d_in, const int* in_sizes, int n_in,
                              void* d_out, int out_size) {
    const float* x    = (const float*)d_in[0];
    const float* grid = (const float*)d_in[1];
    const float* w1b  = (const float*)d_in[2];
    const float* w1s  = (const float*)d_in[3];
    const float* w2b  = (const float*)d_in[4];
    const float* w2s  = (const float*)d_in[5];
    float* out = (float*)d_out;

    const int ntok = in_sizes[0] / D_MODEL;  // 4096

    __nv_bfloat16 *A1, *A2, *W1, *W2;
    float* H;
    cudaGetSymbolAddress((void**)&A1, g_A1);
    cudaGetSymbolAddress((void**)&A2, g_A2);
    cudaGetSymbolAddress((void**)&W1, g_W1);
    cudaGetSymbolAddress((void**)&W2, g_W2);
    cudaGetSymbolAddress((void**)&H,  g_H);

    // layer1: warps 2x4, warp tile 64x32 -> BM=128, BN=128
    // layer2: warps 4x2, warp tile 32x32 -> BM=128, BN=64
    const int smem1 = STAGES * (128 + 128) * LDT * 2;  // 110592
    const int smem2 = STAGES * (128 + 64) * LDT * 2;   //  82944
    cudaFuncSetAttribute((const void*)gemm_mma<2, 4, 4, 4>,
                         cudaFuncAttributeMaxDynamicSharedMemorySize, smem1);
    cudaFuncSetAttribute((const void*)gemm_mma<4, 2, 2, 4>,
                         cudaFuncAttributeMaxDynamicSharedMemorySize, smem2);

    // pack weights
    {
        int n1 = D_FF * D_MODEL;
        pack_w<<<(n1 + 255) / 256, 256>>>(w1b, w1s, W1, n1, 9, K1P);
        int n2 = D_MODEL * D_FF;
        pack_w<<<(n2 + 255) / 256, 256>>>(w2b, w2s, W2, n2, 11, K2P);
    }

    // ---- layer 1 ----
    const int tot1 = ntok * D_MODEL;
    expand_pack<<<(tot1 + 255) / 256, 256>>>(x, grid, A1, tot1, 9, K1P);

    dim3 grid1(D_FF / 128, ntok / 128);
    gemm_mma<2, 4, 4, 4><<<grid1, 256, smem1>>>(A1, W1, H, D_FF, K1P);

    // ---- layer 2 ----
    const int tot2 = ntok * D_FF;
    expand_pack<<<(tot2 + 255) / 256, 256>>>(H, grid, A2, tot2, 11, K2P);

    dim3 grid2(D_MODEL / 64, ntok / 128);
    gemm_mma<4, 2, 2, 4><<<grid2, 256, smem2>>>(A2, W2, out, D_MODEL, K2P);
}

// round 6
// speedup vs baseline: 5.2041x; 1.0092x over previous
#include <cuda_runtime.h>
#include <cuda_bf16.h>
#include <math.h>
#include <stdint.h>

#define D_MODEL 512
#define D_FF    2048
#define GKN     8
#define NTOK    4096

// K-concat layouts:
//  layer1 activations: [bases(4096) | Sh(512) | Sh(512) | Sl(512)]  strideK=5632
//  layer1 weights:     [Ws  (4096)  | Wbh(512)| Wbl(512)| Wbh(512)]
//  layer2 activations: [bases(16384)| Sh(2048)| Sh(2048)| Sl(2048)] strideK=22528
#define K1P (D_MODEL * GKN + 3 * D_MODEL)   // 5632
#define K2P (D_FF * GKN + 3 * D_FF)         // 22528

__device__ __nv_bfloat16 g_A1[(size_t)NTOK * K1P];
__device__ __nv_bfloat16 g_A2[(size_t)NTOK * K2P];
__device__ __nv_bfloat16 g_W1[(size_t)D_FF * K1P];
__device__ __nv_bfloat16 g_W2[(size_t)D_MODEL * K2P];
__device__ float         g_H [(size_t)NTOK * D_FF];

// ---------------------------------------------------------------------------
// PTX helpers (arch-agnostic on .target sm_103)
// ---------------------------------------------------------------------------
__device__ __forceinline__ uint32_t cvta_smem(const void* p) {
    uint32_t a;
    asm("{ .reg .u64 t; cvta.to.shared.u64 t, %1; cvt.u32.u64 %0, t; }" : "=r"(a) : "l"(p));
    return a;
}
__device__ __forceinline__ void cp16(uint32_t s, const void* g) {
    asm volatile("cp.async.cg.shared.global [%0], [%1], 16;" :: "r"(s), "l"(g));
}
__device__ __forceinline__ void cp_commit() {
    asm volatile("cp.async.commit_group;" ::: "memory");
}
template <int N>
__device__ __forceinline__ void cp_wait() {
    asm volatile("cp.async.wait_group %0;" :: "n"(N) : "memory");
}
__device__ __forceinline__ void ldmx4(uint32_t* r, uint32_t a) {
    asm volatile("ldmatrix.sync.aligned.m8n8.x4.shared.b16 {%0,%1,%2,%3}, [%4];"
                 : "=r"(r[0]), "=r"(r[1]), "=r"(r[2]), "=r"(r[3]) : "r"(a));
}
__device__ __forceinline__ void mma16816(float* d, const uint32_t* a, uint32_t b0, uint32_t b1) {
    asm volatile(
        "mma.sync.aligned.m16n8k16.row.col.f32.bf16.bf16.f32 "
        "{%0,%1,%2,%3}, {%4,%5,%6,%7}, {%8,%9}, {%0,%1,%2,%3};"
        : "+f"(d[0]), "+f"(d[1]), "+f"(d[2]), "+f"(d[3])
        : "r"(a[0]), "r"(a[1]), "r"(a[2]), "r"(a[3]), "r"(b0), "r"(b1));
}

// ---------------------------------------------------------------------------
// Expansion into packed K-concat activation buffer.
// ---------------------------------------------------------------------------
__global__ void expand_pack(const float* __restrict__ x,
                            const float* __restrict__ grid,
                            __nv_bfloat16* __restrict__ pA,
                            int total, int in_log2, int strideK) {
    int idx = blockIdx.x * blockDim.x + threadIdx.x;
    if (idx >= total) return;
    const int IN = 1 << in_log2;
    const int row = idx >> in_log2;
    const int i = idx & (IN - 1);

    float v = x[idx];
    float s = v * __fdividef(1.0f, 1.0f + __expf(-v));
    __nv_bfloat16 sh = __float2bfloat16(s);
    __nv_bfloat16 sl = __float2bfloat16(s - __bfloat162float(sh));

    float t[12];
#pragma unroll
    for (int j = 0; j < 12; j++) t[j] = __ldg(grid + j);
    float ih = __fdividef(1.0f, t[1] - t[0]);

    float b[11];
#pragma unroll
    for (int j = 0; j < 11; j++) b[j] = (v >= t[j] && v < t[j + 1]) ? 1.0f : 0.0f;

    const float w1 = ih, w2 = ih * 0.5f, w3 = ih * (1.0f / 3.0f);
#pragma unroll
    for (int q = 0; q < 10; q++)
        b[q] = ((v - t[q]) * b[q] + (t[q + 2] - v) * b[q + 1]) * w1;
#pragma unroll
    for (int q = 0; q < 9; q++)
        b[q] = ((v - t[q]) * b[q] + (t[q + 3] - v) * b[q + 1]) * w2;
#pragma unroll
    for (int q = 0; q < 8; q++)
        b[q] = ((v - t[q]) * b[q] + (t[q + 4] - v) * b[q + 1]) * w3;

    __nv_bfloat162 p0 = __floats2bfloat162_rn(b[0], b[1]);
    __nv_bfloat162 p1 = __floats2bfloat162_rn(b[2], b[3]);
    __nv_bfloat162 p2 = __floats2bfloat162_rn(b[4], b[5]);
    __nv_bfloat162 p3 = __floats2bfloat162_rn(b[6], b[7]);
    uint4 pk;
    pk.x = *(uint32_t*)&p0; pk.y = *(uint32_t*)&p1;
    pk.z = *(uint32_t*)&p2; pk.w = *(uint32_t*)&p3;

    __nv_bfloat16* rowp = pA + (size_t)row * strideK;
    *(uint4*)(rowp + i * 8) = pk;
    const int off = IN * 8;
    rowp[off + i]          = sh;
    rowp[off + IN + i]     = sh;
    rowp[off + 2 * IN + i] = sl;
}

// ---------------------------------------------------------------------------
// Weight packing: [Ws | Wbh | Wbl | Wbh]
// ---------------------------------------------------------------------------
__global__ void pack_w(const float* __restrict__ wb,
                       const float* __restrict__ ws,
                       __nv_bfloat16* __restrict__ pW,
                       int total, int in_log2, int strideK) {
    int idx = blockIdx.x * blockDim.x + threadIdx.x;
    if (idx >= total) return;
    const int IN = 1 << in_log2;
    const int o = idx >> in_log2;
    const int i = idx & (IN - 1);

    float base = wb[idx];
    __nv_bfloat16 hi = __float2bfloat16(base);
    __nv_bfloat16 lo = __float2bfloat16(base - __bfloat162float(hi));

    float4 s0 = ((const float4*)ws)[idx * 2];
    float4 s1 = ((const float4*)ws)[idx * 2 + 1];
    __nv_bfloat162 p0 = __floats2bfloat162_rn(s0.x, s0.y);
    __nv_bfloat162 p1 = __floats2bfloat162_rn(s0.z, s0.w);
    __nv_bfloat162 p2 = __floats2bfloat162_rn(s1.x, s1.y);
    __nv_bfloat162 p3 = __floats2bfloat162_rn(s1.z, s1.w);
    uint4 pk;
    pk.x = *(uint32_t*)&p0; pk.y = *(uint32_t*)&p1;
    pk.z = *(uint32_t*)&p2; pk.w = *(uint32_t*)&p3;

    __nv_bfloat16* rowp = pW + (size_t)o * strideK;
    *(uint4*)(rowp + i * 8) = pk;
    const int off = IN * 8;
    rowp[off + i]          = hi;
    rowp[off + IN + i]     = lo;
    rowp[off + 2 * IN + i] = hi;
}

// ---------------------------------------------------------------------------
// bf16 mma.sync GEMM: C(M,Nout) = A(M,K) * B(Nout,K)^T, fp32 accumulate.
// 4 warps (2x2), warp tile (MI*16) x (NI*8): 64x64 or 64x32.
// BK=64, 3-stage cp.async ring, one __syncthreads per K-iter.
// SMEM rows padded to 72 bf16 (144B) -> conflict-free ldmatrix.
// ---------------------------------------------------------------------------
#define BKK 64
#define STAGES 3
#define LDT 72

template <int MI, int NI>
__global__ void __launch_bounds__(128, 2)
gemm_mma(const __nv_bfloat16* __restrict__ A, const __nv_bfloat16* __restrict__ B,
         float* __restrict__ C, int Nout, int K) {
    constexpr int WM = 2, WN = 2;
    constexpr int BM_ = WM * MI * 16;
    constexpr int BN_ = WN * NI * 8;
    constexpr int TILE_A = BM_ * LDT;
    constexpr int TILE_B = BN_ * LDT;
    extern __shared__ __nv_bfloat16 sm[];
    const uint32_t sm_base = cvta_smem(sm);

    const int tid = threadIdx.x;
    const int lane = tid & 31;
    const int wid = tid >> 5;
    const int wm = wid >> 1;
    const int wn = wid & 1;
    const int m0 = blockIdx.y * BM_;
    const int n0 = blockIdx.x * BN_;

    const __nv_bfloat16* Ag = A + (size_t)m0 * K;
    const __nv_bfloat16* Bg = B + (size_t)n0 * K;

    // loader: 8 threads per 64-elem row (16B each); 128 threads = 16 rows/pass
    const int lrow = tid >> 3;
    const int lcol = (tid & 7) * 8;

    const int nk = K / BKK;

    auto stage_load = [&](int ks) {
        const int buf = ks % STAGES;
        const size_t koff = (size_t)ks * BKK + lcol;
        const uint32_t abase = sm_base + (uint32_t)(buf * (TILE_A + TILE_B)) * 2;
        const uint32_t bbase = abase + (uint32_t)TILE_A * 2;
#pragma unroll
        for (int r = 0; r < BM_; r += 16)
            cp16(abase + (uint32_t)((lrow + r) * LDT + lcol) * 2,
                 Ag + (size_t)(lrow + r) * K + koff);
#pragma unroll
        for (int r = 0; r < BN_; r += 16)
            cp16(bbase + (uint32_t)((lrow + r) * LDT + lcol) * 2,
                 Bg + (size_t)(lrow + r) * K + koff);
        cp_commit();
    };

    float acc[MI][NI][4];
#pragma unroll
    for (int i = 0; i < MI; i++)
#pragma unroll
        for (int j = 0; j < NI; j++)
#pragma unroll
            for (int e = 0; e < 4; e++) acc[i][j][e] = 0.0f;

    const int lm_row = lane & 15;
    const int lm_koff = (lane >> 4) * 8;

    stage_load(0);
    stage_load(1);

    for (int ks = 0; ks < nk; ks++) {
        if (ks + 1 < nk) cp_wait<1>(); else cp_wait<0>();
        __syncthreads();
        if (ks + 2 < nk) stage_load(ks + 2);

        const int buf = ks % STAGES;
        const uint32_t abase = sm_base + (uint32_t)(buf * (TILE_A + TILE_B)) * 2;
        const uint32_t bbase = abase + (uint32_t)TILE_A * 2;

#pragma unroll
        for (int kf = 0; kf < 4; kf++) {
            uint32_t afr[MI][4];
#pragma unroll
            for (int mi = 0; mi < MI; mi++) {
                uint32_t addr = abase +
                    (uint32_t)((wm * MI * 16 + mi * 16 + lm_row) * LDT + kf * 16 + lm_koff) * 2;
                ldmx4(afr[mi], addr);
            }
            uint32_t bfr[NI / 2][4];
#pragma unroll
            for (int g = 0; g < NI / 2; g++) {
                uint32_t addr = bbase +
                    (uint32_t)((wn * NI * 8 + g * 16 + lm_row) * LDT + kf * 16 + lm_koff) * 2;
                ldmx4(bfr[g], addr);
            }
#pragma unroll
            for (int mi = 0; mi < MI; mi++)
#pragma unroll
                for (int ni = 0; ni < NI; ni++) {
                    const int g = ni >> 1, o = ni & 1;
                    mma16816(acc[mi][ni], afr[mi], bfr[g][o], bfr[g][o + 2]);
                }
        }
    }

    // epilogue
    const int erow = lane >> 2;
    const int ecol = (lane & 3) * 2;
#pragma unroll
    for (int mi = 0; mi < MI; mi++) {
#pragma unroll
        for (int ni = 0; ni < NI; ni++) {
            const int row = m0 + wm * MI * 16 + mi * 16 + erow;
            const int col = n0 + wn * NI * 8 + ni * 8 + ecol;
            float* p0 = C + (size_t)row * Nout + col;
            float* p1 = C + (size_t)(row + 8) * Nout + col;
            *(float2*)p0 = make_float2(acc[mi][ni][0], acc[mi][ni][1]);
            *(float2*)p1 = make_float2(acc[mi][ni][2], acc[mi][ni][3]);
        }
    }
}

// ---------------------------------------------------------------------------
// Launch
// ---------------------------------------------------------------------------
extern "C" void kernel_launch(void* const* d_in, const int* in_sizes, int n_in,
                              void* d_out, int out_size) {
    const float* x    = (const float*)d_in[0];
    const float* grid = (const float*)d_in[1];
    const float* w1b  = (const float*)d_in[2];
    const float* w1s  = (const float*)d_in[3];
    const float* w2b  = (const float*)d_in[4];
    const float* w2s  = (const float*)d_in[5];
    float* out = (float*)d_out;

    const int ntok = in_sizes[0] / D_MODEL;  // 4096

    __nv_bfloat16 *A1, *A2, *W1, *W2;
    float* H;
    cudaGetSymbolAddress((void**)&A1, g_A1);
    cudaGetSymbolAddress((void**)&A2, g_A2);
    cudaGetSymbolAddress((void**)&W1, g_W1);
    cudaGetSymbolAddress((void**)&W2, g_W2);
    cudaGetSymbolAddress((void**)&H,  g_H);

    // layer1: 4 warps 2x2, warp tile 64x64 -> BM=128, BN=128
    // layer2: 4 warps 2x2, warp tile 64x32 -> BM=128, BN=64
    const int smem1 = STAGES * (128 + 128) * LDT * 2;  // 110592
    const int smem2 = STAGES * (128 + 64) * LDT * 2;   //  82944
    cudaFuncSetAttribute((const void*)gemm_mma<4, 8>,
                         cudaFuncAttributeMaxDynamicSharedMemorySize, smem1);
    cudaFuncSetAttribute((const void*)gemm_mma<4, 4>,
                         cudaFuncAttributeMaxDynamicSharedMemorySize, smem2);

    // pack weights
    {
        int n1 = D_FF * D_MODEL;
        pack_w<<<(n1 + 255) / 256, 256>>>(w1b, w1s, W1, n1, 9, K1P);
        int n2 = D_MODEL * D_FF;
        pack_w<<<(n2 + 255) / 256, 256>>>(w2b, w2s, W2, n2, 11, K2P);
    }

    // ---- layer 1 ----
    const int tot1 = ntok * D_MODEL;
    expand_pack<<<(tot1 + 255) / 256, 256>>>(x, grid, A1, tot1, 9, K1P);

    dim3 grid1(D_FF / 128, ntok / 128);
    gemm_mma<4, 8><<<grid1, 128, smem1>>>(A1, W1, H, D_FF, K1P);

    // ---- layer 2 ----
    const int tot2 = ntok * D_FF;
    expand_pack<<<(tot2 + 255) / 256, 256>>>(H, grid, A2, tot2, 11, K2P);

    dim3 grid2(D_MODEL / 64, ntok / 128);
    gemm_mma<4, 4><<<grid2, 128, smem2>>>(A2, W2, out, D_MODEL, K2P);
}

// round 7
// speedup vs baseline: 5.2161x; 1.0023x over previous
#include <cuda_runtime.h>
#include <cuda_bf16.h>
#include <math.h>
#include <stdint.h>

#define D_MODEL 512
#define D_FF    2048
#define GKN     8
#define NTOK    4096

// K-concat layouts:
//  layer1 activations: [bases(4096) | Sh(512) | Sh(512) | Sl(512)]  strideK=5632
//  layer1 weights:     [Ws  (4096)  | Wbh(512)| Wbl(512)| Wbh(512)]
//  layer2 activations: [bases(16384)| Sh(2048)| Sh(2048)| Sl(2048)] strideK=22528
#define K1P (D_MODEL * GKN + 3 * D_MODEL)   // 5632
#define K2P (D_FF * GKN + 3 * D_FF)         // 22528

__device__ __nv_bfloat16 g_A1[(size_t)NTOK * K1P];
__device__ __nv_bfloat16 g_A2[(size_t)NTOK * K2P];
__device__ __nv_bfloat16 g_W1[(size_t)D_FF * K1P];
__device__ __nv_bfloat16 g_W2[(size_t)D_MODEL * K2P];
__device__ float         g_H [(size_t)NTOK * D_FF];

// ---------------------------------------------------------------------------
// PTX helpers (arch-agnostic on .target sm_103)
// ---------------------------------------------------------------------------
__device__ __forceinline__ uint32_t cvta_smem(const void* p) {
    uint32_t a;
    asm("{ .reg .u64 t; cvta.to.shared.u64 t, %1; cvt.u32.u64 %0, t; }" : "=r"(a) : "l"(p));
    return a;
}
__device__ __forceinline__ void cp16(uint32_t s, const void* g) {
    asm volatile("cp.async.cg.shared.global [%0], [%1], 16;" :: "r"(s), "l"(g));
}
__device__ __forceinline__ void cp_commit() {
    asm volatile("cp.async.commit_group;" ::: "memory");
}
template <int N>
__device__ __forceinline__ void cp_wait() {
    asm volatile("cp.async.wait_group %0;" :: "n"(N) : "memory");
}
__device__ __forceinline__ void ldmx4(uint32_t* r, uint32_t a) {
    asm volatile("ldmatrix.sync.aligned.m8n8.x4.shared.b16 {%0,%1,%2,%3}, [%4];"
                 : "=r"(r[0]), "=r"(r[1]), "=r"(r[2]), "=r"(r[3]) : "r"(a));
}
__device__ __forceinline__ void mma16816(float* d, const uint32_t* a, uint32_t b0, uint32_t b1) {
    asm volatile(
        "mma.sync.aligned.m16n8k16.row.col.f32.bf16.bf16.f32 "
        "{%0,%1,%2,%3}, {%4,%5,%6,%7}, {%8,%9}, {%0,%1,%2,%3};"
        : "+f"(d[0]), "+f"(d[1]), "+f"(d[2]), "+f"(d[3])
        : "r"(a[0]), "r"(a[1]), "r"(a[2]), "r"(a[3]), "r"(b0), "r"(b1));
}

// ---------------------------------------------------------------------------
// Expansion into packed K-concat activation buffer.
// ---------------------------------------------------------------------------
__global__ void expand_pack(const float* __restrict__ x,
                            const float* __restrict__ grid,
                            __nv_bfloat16* __restrict__ pA,
                            int total, int in_log2, int strideK) {
    int idx = blockIdx.x * blockDim.x + threadIdx.x;
    if (idx >= total) return;
    const int IN = 1 << in_log2;
    const int row = idx >> in_log2;
    const int i = idx & (IN - 1);

    float v = x[idx];
    float s = v * __fdividef(1.0f, 1.0f + __expf(-v));
    __nv_bfloat16 sh = __float2bfloat16(s);
    __nv_bfloat16 sl = __float2bfloat16(s - __bfloat162float(sh));

    float t[12];
#pragma unroll
    for (int j = 0; j < 12; j++) t[j] = __ldg(grid + j);
    float ih = __fdividef(1.0f, t[1] - t[0]);

    float b[11];
#pragma unroll
    for (int j = 0; j < 11; j++) b[j] = (v >= t[j] && v < t[j + 1]) ? 1.0f : 0.0f;

    const float w1 = ih, w2 = ih * 0.5f, w3 = ih * (1.0f / 3.0f);
#pragma unroll
    for (int q = 0; q < 10; q++)
        b[q] = ((v - t[q]) * b[q] + (t[q + 2] - v) * b[q + 1]) * w1;
#pragma unroll
    for (int q = 0; q < 9; q++)
        b[q] = ((v - t[q]) * b[q] + (t[q + 3] - v) * b[q + 1]) * w2;
#pragma unroll
    for (int q = 0; q < 8; q++)
        b[q] = ((v - t[q]) * b[q] + (t[q + 4] - v) * b[q + 1]) * w3;

    __nv_bfloat162 p0 = __floats2bfloat162_rn(b[0], b[1]);
    __nv_bfloat162 p1 = __floats2bfloat162_rn(b[2], b[3]);
    __nv_bfloat162 p2 = __floats2bfloat162_rn(b[4], b[5]);
    __nv_bfloat162 p3 = __floats2bfloat162_rn(b[6], b[7]);
    uint4 pk;
    pk.x = *(uint32_t*)&p0; pk.y = *(uint32_t*)&p1;
    pk.z = *(uint32_t*)&p2; pk.w = *(uint32_t*)&p3;

    __nv_bfloat16* rowp = pA + (size_t)row * strideK;
    *(uint4*)(rowp + i * 8) = pk;
    const int off = IN * 8;
    rowp[off + i]          = sh;
    rowp[off + IN + i]     = sh;
    rowp[off + 2 * IN + i] = sl;
}

// ---------------------------------------------------------------------------
// Weight packing: [Ws | Wbh | Wbl | Wbh]
// ---------------------------------------------------------------------------
__global__ void pack_w(const float* __restrict__ wb,
                       const float* __restrict__ ws,
                       __nv_bfloat16* __restrict__ pW,
                       int total, int in_log2, int strideK) {
    int idx = blockIdx.x * blockDim.x + threadIdx.x;
    if (idx >= total) return;
    const int IN = 1 << in_log2;
    const int o = idx >> in_log2;
    const int i = idx & (IN - 1);

    float base = wb[idx];
    __nv_bfloat16 hi = __float2bfloat16(base);
    __nv_bfloat16 lo = __float2bfloat16(base - __bfloat162float(hi));

    float4 s0 = ((const float4*)ws)[idx * 2];
    float4 s1 = ((const float4*)ws)[idx * 2 + 1];
    __nv_bfloat162 p0 = __floats2bfloat162_rn(s0.x, s0.y);
    __nv_bfloat162 p1 = __floats2bfloat162_rn(s0.z, s0.w);
    __nv_bfloat162 p2 = __floats2bfloat162_rn(s1.x, s1.y);
    __nv_bfloat162 p3 = __floats2bfloat162_rn(s1.z, s1.w);
    uint4 pk;
    pk.x = *(uint32_t*)&p0; pk.y = *(uint32_t*)&p1;
    pk.z = *(uint32_t*)&p2; pk.w = *(uint32_t*)&p3;

    __nv_bfloat16* rowp = pW + (size_t)o * strideK;
    *(uint4*)(rowp + i * 8) = pk;
    const int off = IN * 8;
    rowp[off + i]          = hi;
    rowp[off + IN + i]     = lo;
    rowp[off + 2 * IN + i] = hi;
}

// ---------------------------------------------------------------------------
// bf16 mma.sync GEMM: C(M,Nout) = A(M,K) * B(Nout,K)^T, fp32 accumulate.
// 4 warps (2x2), warp tile (MI*16) x (NI*8).
// BK=64, 3-stage cp.async ring, one __syncthreads per K-iter,
// MANUAL fragment double-buffering across kf phases (LDSM hidden under HMMA).
// SMEM rows padded to 72 bf16 (144B) -> conflict-free ldmatrix.
// ---------------------------------------------------------------------------
#define BKK 64
#define STAGES 3
#define LDT 72

template <int MI, int NI>
__global__ void __launch_bounds__(128, 2)
gemm_mma(const __nv_bfloat16* __restrict__ A, const __nv_bfloat16* __restrict__ B,
         float* __restrict__ C, int Nout, int K) {
    constexpr int BM_ = 2 * MI * 16;
    constexpr int BN_ = 2 * NI * 8;
    constexpr int TILE_A = BM_ * LDT;
    constexpr int TILE_B = BN_ * LDT;
    extern __shared__ __nv_bfloat16 sm[];
    const uint32_t sm_base = cvta_smem(sm);

    const int tid = threadIdx.x;
    const int lane = tid & 31;
    const int wid = tid >> 5;
    const int wm = wid >> 1;
    const int wn = wid & 1;
    const int m0 = blockIdx.y * BM_;
    const int n0 = blockIdx.x * BN_;

    const __nv_bfloat16* Ag = A + (size_t)m0 * K;
    const __nv_bfloat16* Bg = B + (size_t)n0 * K;

    // loader: 8 threads per 64-elem row (16B each); 128 threads = 16 rows/pass
    const int lrow = tid >> 3;
    const int lcol = (tid & 7) * 8;

    const int nk = K / BKK;

    auto stage_load = [&](int ks) {
        const int buf = ks % STAGES;
        const size_t koff = (size_t)ks * BKK + lcol;
        const uint32_t abase = sm_base + (uint32_t)(buf * (TILE_A + TILE_B)) * 2;
        const uint32_t bbase = abase + (uint32_t)TILE_A * 2;
#pragma unroll
        for (int r = 0; r < BM_; r += 16)
            cp16(abase + (uint32_t)((lrow + r) * LDT + lcol) * 2,
                 Ag + (size_t)(lrow + r) * K + koff);
#pragma unroll
        for (int r = 0; r < BN_; r += 16)
            cp16(bbase + (uint32_t)((lrow + r) * LDT + lcol) * 2,
                 Bg + (size_t)(lrow + r) * K + koff);
        cp_commit();
    };

    float acc[MI][NI][4];
#pragma unroll
    for (int i = 0; i < MI; i++)
#pragma unroll
        for (int j = 0; j < NI; j++)
#pragma unroll
            for (int e = 0; e < 4; e++) acc[i][j][e] = 0.0f;

    const int lm_row = lane & 15;
    const int lm_koff = (lane >> 4) * 8;

    // double-buffered fragments
    uint32_t afr[2][MI][4];
    uint32_t bfr[2][NI / 2][4];

    stage_load(0);
    stage_load(1);

    for (int ks = 0; ks < nk; ks++) {
        if (ks + 1 < nk) cp_wait<1>(); else cp_wait<0>();
        __syncthreads();
        if (ks + 2 < nk) stage_load(ks + 2);

        const int buf = ks % STAGES;
        const uint32_t abase = sm_base + (uint32_t)(buf * (TILE_A + TILE_B)) * 2 +
                               (uint32_t)((wm * MI * 16 + lm_row) * LDT + lm_koff) * 2;
        const uint32_t bbase = sm_base + (uint32_t)(buf * (TILE_A + TILE_B) + TILE_A) * 2 +
                               (uint32_t)((wn * NI * 8 + lm_row) * LDT + lm_koff) * 2;

        // preload phase 0 fragments
#pragma unroll
        for (int mi = 0; mi < MI; mi++)
            ldmx4(afr[0][mi], abase + (uint32_t)(mi * 16 * LDT) * 2);
#pragma unroll
        for (int g = 0; g < NI / 2; g++)
            ldmx4(bfr[0][g], bbase + (uint32_t)(g * 16 * LDT) * 2);

#pragma unroll
        for (int kf = 0; kf < 4; kf++) {
            const int cur = kf & 1, nxt = cur ^ 1;
            // issue next phase's LDSMs first (hidden under this phase's MMAs)
            if (kf < 3) {
                const uint32_t ka = abase + (uint32_t)((kf + 1) * 16) * 2;
                const uint32_t kb = bbase + (uint32_t)((kf + 1) * 16) * 2;
#pragma unroll
                for (int mi = 0; mi < MI; mi++)
                    ldmx4(afr[nxt][mi], ka + (uint32_t)(mi * 16 * LDT) * 2);
#pragma unroll
                for (int g = 0; g < NI / 2; g++)
                    ldmx4(bfr[nxt][g], kb + (uint32_t)(g * 16 * LDT) * 2);
            }
#pragma unroll
            for (int mi = 0; mi < MI; mi++)
#pragma unroll
                for (int ni = 0; ni < NI; ni++) {
                    const int g = ni >> 1, o = ni & 1;
                    mma16816(acc[mi][ni], afr[cur][mi], bfr[cur][g][o], bfr[cur][g][o + 2]);
                }
        }
    }

    // epilogue
    const int erow = lane >> 2;
    const int ecol = (lane & 3) * 2;
#pragma unroll
    for (int mi = 0; mi < MI; mi++) {
#pragma unroll
        for (int ni = 0; ni < NI; ni++) {
            const int row = m0 + wm * MI * 16 + mi * 16 + erow;
            const int col = n0 + wn * NI * 8 + ni * 8 + ecol;
            float* p0 = C + (size_t)row * Nout + col;
            float* p1 = C + (size_t)(row + 8) * Nout + col;
            *(float2*)p0 = make_float2(acc[mi][ni][0], acc[mi][ni][1]);
            *(float2*)p1 = make_float2(acc[mi][ni][2], acc[mi][ni][3]);
        }
    }
}

// ---------------------------------------------------------------------------
// Launch
// ---------------------------------------------------------------------------
extern "C" void kernel_launch(void* const* d_in, const int* in_sizes, int n_in,
                              void* d_out, int out_size) {
    const float* x    = (const float*)d_in[0];
    const float* grid = (const float*)d_in[1];
    const float* w1b  = (const float*)d_in[2];
    const float* w1s  = (const float*)d_in[3];
    const float* w2b  = (const float*)d_in[4];
    const float* w2s  = (const float*)d_in[5];
    float* out = (float*)d_out;

    const int ntok = in_sizes[0] / D_MODEL;  // 4096

    __nv_bfloat16 *A1, *A2, *W1, *W2;
    float* H;
    cudaGetSymbolAddress((void**)&A1, g_A1);
    cudaGetSymbolAddress((void**)&A2, g_A2);
    cudaGetSymbolAddress((void**)&W1, g_W1);
    cudaGetSymbolAddress((void**)&W2, g_W2);
    cudaGetSymbolAddress((void**)&H,  g_H);

    // layer1: 4 warps 2x2, warp tile 64x64 -> BM=128, BN=128
    // layer2: 4 warps 2x2, warp tile 64x32 -> BM=128, BN=64
    const int smem1 = STAGES * (128 + 128) * LDT * 2;  // 110592
    const int smem2 = STAGES * (128 + 64) * LDT * 2;   //  82944
    cudaFuncSetAttribute((const void*)gemm_mma<4, 8>,
                         cudaFuncAttributeMaxDynamicSharedMemorySize, smem1);
    cudaFuncSetAttribute((const void*)gemm_mma<4, 4>,
                         cudaFuncAttributeMaxDynamicSharedMemorySize, smem2);

    // pack weights
    {
        int n1 = D_FF * D_MODEL;
        pack_w<<<(n1 + 255) / 256, 256>>>(w1b, w1s, W1, n1, 9, K1P);
        int n2 = D_MODEL * D_FF;
        pack_w<<<(n2 + 255) / 256, 256>>>(w2b, w2s, W2, n2, 11, K2P);
    }

    // ---- layer 1 ----
    const int tot1 = ntok * D_MODEL;
    expand_pack<<<(tot1 + 255) / 256, 256>>>(x, grid, A1, tot1, 9, K1P);

    dim3 grid1(D_FF / 128, ntok / 128);
    gemm_mma<4, 8><<<grid1, 128, smem1>>>(A1, W1, H, D_FF, K1P);

    // ---- layer 2 ----
    const int tot2 = ntok * D_FF;
    expand_pack<<<(tot2 + 255) / 256, 256>>>(H, grid, A2, tot2, 11, K2P);

    dim3 grid2(D_MODEL / 64, ntok / 128);
    gemm_mma<4, 4><<<grid2, 128, smem2>>>(A2, W2, out, D_MODEL, K2P);
}